// round 1
// baseline (speedup 1.0000x reference)
#include <cuda_runtime.h>
#include <math.h>

#define NN   50000
#define NE   800000
#define ET   850000   // NE + NN self loops
#define IND  256
#define HID  128
#define NG   64
#define NEG_SLOPE 0.2f

// ---------------- scratch (no allocations allowed) ----------------
__device__ float g_bufA[NN * HID];   // 25.6 MB
__device__ float g_bufB[NN * HID];   // 25.6 MB
__device__ float g_as[NN];
__device__ float g_ad[NN];
__device__ float g_m[NN];
__device__ float g_den[NN];
__device__ float g_w[ET];
__device__ int   g_src[ET];
__device__ int   g_dst[ET];
__device__ int   g_batch[NN];
__device__ float g_pool[NG * HID];
__device__ int   g_cnt[NG];
__device__ int   g_flag[2];          // [0]=edge_index is int64, [1]=batch is int64

// ---------------- dtype sniffing (int64 vs int32) ----------------
// edge values < 50000, batch values < 64. If stored as int64 (LE), every odd
// 32-bit word is a zero high-word. If int32, odd words are data values.
__global__ void detect_kernel(const unsigned* __restrict__ e,
                              const unsigned* __restrict__ b) {
    if (threadIdx.x == 0 && blockIdx.x == 0) {
        int nz = 0;
        for (int i = 0; i < 1024; i++) nz += (e[2 * i + 1] != 0u);   // words < 2048 (safe either way)
        g_flag[0] = (nz == 0);
        nz = 0;
        // sample odd words near the END of the int32-sized window [0, NN):
        // batch is sorted, so tail values are ~63 (nonzero) in int32 case.
        for (int i = 0; i < 256; i++) nz += (b[NN - 1 - 2 * i] != 0u);
        g_flag[1] = (nz == 0);
    }
}

__global__ void convert_kernel(const void* __restrict__ edge,
                               const void* __restrict__ batch) {
    int e64 = g_flag[0], b64 = g_flag[1];
    int stride = gridDim.x * blockDim.x;
    for (int i = blockIdx.x * blockDim.x + threadIdx.x; i < ET; i += stride) {
        if (i < NE) {
            int s, d;
            if (e64) {
                s = (int)((const long long*)edge)[i];
                d = (int)((const long long*)edge)[NE + i];
            } else {
                s = ((const int*)edge)[i];
                d = ((const int*)edge)[NE + i];
            }
            g_src[i] = s; g_dst[i] = d;
        } else {
            int j = i - NE;
            g_src[i] = j; g_dst[i] = j;
        }
        if (i < NN) {
            g_batch[i] = b64 ? (int)((const long long*)batch)[i]
                             : ((const int*)batch)[i];
        }
    }
}

// ---------------- init ----------------
// which==1 -> also zero bufA (layer2 out accumulator)
// which==0 -> zero bufB (layer1 out accumulator) + pool/cnt
__global__ void init_kernel(int which) {
    int stride = gridDim.x * blockDim.x;
    int i0 = blockIdx.x * blockDim.x + threadIdx.x;
    float* z = which ? g_bufA : g_bufB;
    for (int j = i0; j < NN * HID; j += stride) z[j] = 0.f;
    for (int j = i0; j < NN; j += stride) { g_m[j] = -INFINITY; g_den[j] = 0.f; }
    if (which == 0) {
        for (int j = i0; j < NG * HID; j += stride) g_pool[j] = 0.f;
        for (int j = i0; j < NG; j += stride) g_cnt[j] = 0;
    }
}

// ---------------- SGEMM: C[M,128] = A[M,K] @ B[K,128] ----------------
template <int K>
__global__ void __launch_bounds__(256)
gemm_kernel(const float* __restrict__ A, const float* __restrict__ B,
            float* __restrict__ C, int M) {
    const int BM = 64, BN = 128, BK = 16;
    __shared__ float As[BK][BM];
    __shared__ float Bs[BK][BN];
    int tid = threadIdx.x;
    int m0 = blockIdx.x * BM;
    int ty = tid >> 5;        // 0..7 -> rows ty*8 .. ty*8+7
    int tx = tid & 31;        // cols tx*4 .. tx*4+3

    float acc[8][4];
#pragma unroll
    for (int i = 0; i < 8; i++)
#pragma unroll
        for (int j = 0; j < 4; j++) acc[i][j] = 0.f;

    int arow = tid >> 2;            // 0..63
    int ak4  = (tid & 3) * 4;       // 0,4,8,12
    int bn4  = (tid & 31) * 4;      // 0..124
    int bk   = tid >> 5;            // 0..7

    for (int k0 = 0; k0 < K; k0 += BK) {
        float4 av = make_float4(0.f, 0.f, 0.f, 0.f);
        int gm = m0 + arow;
        if (gm < M) av = *(const float4*)(A + (size_t)gm * K + k0 + ak4);
        As[ak4 + 0][arow] = av.x; As[ak4 + 1][arow] = av.y;
        As[ak4 + 2][arow] = av.z; As[ak4 + 3][arow] = av.w;

        float4 bv0 = *(const float4*)(B + (size_t)(k0 + bk) * BN + bn4);
        float4 bv1 = *(const float4*)(B + (size_t)(k0 + bk + 8) * BN + bn4);
        *(float4*)&Bs[bk][bn4]     = bv0;
        *(float4*)&Bs[bk + 8][bn4] = bv1;
        __syncthreads();

#pragma unroll
        for (int k = 0; k < BK; k++) {
            float4 b4 = *(const float4*)&Bs[k][tx * 4];
            float4 a0 = *(const float4*)&As[k][ty * 8];
            float4 a1 = *(const float4*)&As[k][ty * 8 + 4];
            float a[8] = {a0.x, a0.y, a0.z, a0.w, a1.x, a1.y, a1.z, a1.w};
#pragma unroll
            for (int i = 0; i < 8; i++) {
                acc[i][0] += a[i] * b4.x;
                acc[i][1] += a[i] * b4.y;
                acc[i][2] += a[i] * b4.z;
                acc[i][3] += a[i] * b4.w;
            }
        }
        __syncthreads();
    }

#pragma unroll
    for (int i = 0; i < 8; i++) {
        int gm = m0 + ty * 8 + i;
        if (gm < M)
            *(float4*)(C + (size_t)gm * BN + tx * 4) =
                make_float4(acc[i][0], acc[i][1], acc[i][2], acc[i][3]);
    }
}

// ---------------- per-node attention scalars ----------------
__global__ void alpha_kernel(const float* __restrict__ h,
                             const float* __restrict__ asrc,
                             const float* __restrict__ adst) {
    int node = blockIdx.x * (blockDim.x >> 5) + (threadIdx.x >> 5);
    if (node >= NN) return;
    int lane = threadIdx.x & 31;
    float s = 0.f, d = 0.f;
#pragma unroll
    for (int j = lane; j < HID; j += 32) {
        float hv = h[(size_t)node * HID + j];
        s += hv * asrc[j];
        d += hv * adst[j];
    }
#pragma unroll
    for (int o = 16; o; o >>= 1) {
        s += __shfl_xor_sync(0xffffffffu, s, o);
        d += __shfl_xor_sync(0xffffffffu, d, o);
    }
    if (lane == 0) { g_as[node] = s; g_ad[node] = d; }
}

// ---------------- edge passes ----------------
__device__ __forceinline__ void atomicMaxF(float* addr, float val) {
    if (val >= 0.f) atomicMax((int*)addr, __float_as_int(val));
    else            atomicMin((unsigned int*)addr, __float_as_uint(val));
}

__global__ void edge_max_kernel() {
    int i = blockIdx.x * blockDim.x + threadIdx.x;
    if (i >= ET) return;
    int s = g_src[i], d = g_dst[i];
    float e = g_as[s] + g_ad[d];
    e = e > 0.f ? e : NEG_SLOPE * e;
    atomicMaxF(&g_m[d], e);
}

__global__ void edge_exp_kernel() {
    int i = blockIdx.x * blockDim.x + threadIdx.x;
    if (i >= ET) return;
    int s = g_src[i], d = g_dst[i];
    float e = g_as[s] + g_ad[d];
    e = e > 0.f ? e : NEG_SLOPE * e;
    float w = expf(e - g_m[d]);
    g_w[i] = w;
    atomicAdd(&g_den[d], w);
}

// warp per edge; lane handles 4 contiguous dims (float4 gather + 4 red.adds)
__global__ void __launch_bounds__(256)
scatter_kernel(const float* __restrict__ h, float* __restrict__ out) {
    int e = blockIdx.x * 8 + (threadIdx.x >> 5);
    if (e >= ET) return;
    int lane = threadIdx.x & 31;
    int s = g_src[e], d = g_dst[e];
    float coef = g_w[e] / g_den[d];
    float4 hv = ((const float4*)(h + (size_t)s * HID))[lane];
    float* o = out + (size_t)d * HID + lane * 4;
    atomicAdd(o + 0, hv.x * coef);
    atomicAdd(o + 1, hv.y * coef);
    atomicAdd(o + 2, hv.z * coef);
    atomicAdd(o + 3, hv.w * coef);
}

// ---------------- epilogues ----------------
__global__ void epi1_kernel(const float* __restrict__ in,
                            const float* __restrict__ b,
                            float* __restrict__ out) {
    int i = blockIdx.x * blockDim.x + threadIdx.x;
    if (i >= NN * HID / 4) return;
    float4 v = ((const float4*)in)[i];
    float4 bb = ((const float4*)b)[i & 31];
    v.x = fmaxf(v.x + bb.x, 0.f);
    v.y = fmaxf(v.y + bb.y, 0.f);
    v.z = fmaxf(v.z + bb.z, 0.f);
    v.w = fmaxf(v.w + bb.w, 0.f);
    ((float4*)out)[i] = v;
}

__global__ void epi2pool_kernel(const float* __restrict__ in,
                                const float* __restrict__ b) {
    int node = blockIdx.x * (blockDim.x >> 5) + (threadIdx.x >> 5);
    if (node >= NN) return;
    int lane = threadIdx.x & 31;
    int g = g_batch[node];
    float4 v = ((const float4*)(in + (size_t)node * HID))[lane];
    float4 bb = ((const float4*)b)[lane];
    v.x = fmaxf(v.x + bb.x, 0.f);
    v.y = fmaxf(v.y + bb.y, 0.f);
    v.z = fmaxf(v.z + bb.z, 0.f);
    v.w = fmaxf(v.w + bb.w, 0.f);
    float* p = g_pool + g * HID + lane * 4;
    atomicAdd(p + 0, v.x);
    atomicAdd(p + 1, v.y);
    atomicAdd(p + 2, v.z);
    atomicAdd(p + 3, v.w);
    if (lane == 0) atomicAdd(&g_cnt[g], 1);
}

__global__ void head_kernel(const float* __restrict__ Wc,
                            const float* __restrict__ bc,
                            float* __restrict__ out) {
    int g = blockIdx.x;
    int lane = threadIdx.x;
    float s = 0.f;
#pragma unroll
    for (int j = lane; j < HID; j += 32) s += g_pool[g * HID + j] * Wc[j];
#pragma unroll
    for (int o = 16; o; o >>= 1) s += __shfl_xor_sync(0xffffffffu, s, o);
    if (lane == 0) {
        float c = fmaxf((float)g_cnt[g], 1.f);
        float v = s / c + bc[0];
        out[g] = 1.f / (1.f + expf(-v));
    }
}

// ---------------- launch ----------------
extern "C" void kernel_launch(void* const* d_in, const int* in_sizes, int n_in,
                              void* d_out, int out_size) {
    const float* x    = (const float*)d_in[0];
    const void*  edge = d_in[1];
    const void*  batch= d_in[2];
    const float* W1   = (const float*)d_in[3];
    const float* as1  = (const float*)d_in[4];
    const float* ad1  = (const float*)d_in[5];
    const float* b1   = (const float*)d_in[6];
    const float* W2   = (const float*)d_in[7];
    const float* as2  = (const float*)d_in[8];
    const float* ad2  = (const float*)d_in[9];
    const float* b2   = (const float*)d_in[10];
    const float* Wc   = (const float*)d_in[11];
    const float* bc   = (const float*)d_in[12];
    float* out = (float*)d_out;
    (void)in_sizes; (void)n_in; (void)out_size;

    float* bufA; cudaGetSymbolAddress((void**)&bufA, g_bufA);
    float* bufB; cudaGetSymbolAddress((void**)&bufB, g_bufB);

    const int EB = (ET + 255) / 256;        // per-edge kernels
    const int SB = (ET + 7) / 8;            // warp-per-edge scatter (256 thr)
    const int WB = (NN + 7) / 8;            // warp-per-node kernels (256 thr)

    detect_kernel<<<1, 32>>>((const unsigned*)edge, (const unsigned*)batch);
    convert_kernel<<<EB, 256>>>(edge, batch);

    // ---- layer 1 ----
    init_kernel<<<512, 256>>>(0);                      // zero bufB + pool/cnt, m/den
    gemm_kernel<IND><<<(NN + 63) / 64, 256>>>(x, W1, bufA, NN);
    alpha_kernel<<<WB, 256>>>(bufA, as1, ad1);
    edge_max_kernel<<<EB, 256>>>();
    edge_exp_kernel<<<EB, 256>>>();
    scatter_kernel<<<SB, 256>>>(bufA, bufB);
    epi1_kernel<<<(NN * HID / 4 + 255) / 256, 256>>>(bufB, b1, bufA);

    // ---- layer 2 ----
    gemm_kernel<HID><<<(NN + 63) / 64, 256>>>(bufA, W2, bufB, NN);
    init_kernel<<<512, 256>>>(1);                      // zero bufA, reset m/den
    alpha_kernel<<<WB, 256>>>(bufB, as2, ad2);
    edge_max_kernel<<<EB, 256>>>();
    edge_exp_kernel<<<EB, 256>>>();
    scatter_kernel<<<SB, 256>>>(bufB, bufA);
    epi2pool_kernel<<<WB, 256>>>(bufA, b2);

    head_kernel<<<NG, 32>>>(Wc, bc, out);
}

// round 2
// speedup vs baseline: 1.5351x; 1.5351x over previous
#include <cuda_runtime.h>
#include <math.h>

#define NN   50000
#define NE   800000
#define ET   850000   // NE + NN self loops
#define IND  256
#define HID  128
#define NG   64
#define NEG_SLOPE 0.2f

// ---------------- scratch (no allocations allowed) ----------------
__device__ float g_bufA[NN * HID];   // 25.6 MB
__device__ float g_bufB[NN * HID];   // 25.6 MB
__device__ float g_as[NN];
__device__ float g_ad[NN];
__device__ int   g_src[ET];
__device__ int   g_dstv[ET];
__device__ int   g_batch[NN];
__device__ int   g_counts[NN];
__device__ int   g_roff[NN + 1];
__device__ int   g_cursor[NN];
__device__ int   g_csr[ET];          // src node id per CSR slot (grouped by dst)
__device__ float g_pool[NG * HID];
__device__ int   g_gcnt[NG];
__device__ int   g_flag[2];

// ---------------- dtype sniffing (int64 vs int32) ----------------
__global__ void detect_kernel(const unsigned* __restrict__ e,
                              const unsigned* __restrict__ b) {
    if (threadIdx.x == 0 && blockIdx.x == 0) {
        int nz = 0;
        for (int i = 0; i < 1024; i++) nz += (e[2 * i + 1] != 0u);
        g_flag[0] = (nz == 0);
        nz = 0;
        for (int i = 0; i < 256; i++) nz += (b[NN - 1 - 2 * i] != 0u);
        g_flag[1] = (nz == 0);
    }
}

// ---------------- zero small scratch ----------------
__global__ void zero_kernel() {
    int stride = gridDim.x * blockDim.x;
    int i0 = blockIdx.x * blockDim.x + threadIdx.x;
    for (int j = i0; j < NN; j += stride) g_counts[j] = 0;
    for (int j = i0; j < NG * HID; j += stride) g_pool[j] = 0.f;
    for (int j = i0; j < NG; j += stride) g_gcnt[j] = 0;
}

// ---------------- convert + histogram + per-graph counts ----------------
__global__ void convert_kernel(const void* __restrict__ edge,
                               const void* __restrict__ batch) {
    int e64 = g_flag[0], b64 = g_flag[1];
    int stride = gridDim.x * blockDim.x;
    for (int i = blockIdx.x * blockDim.x + threadIdx.x; i < ET; i += stride) {
        int s, d;
        if (i < NE) {
            if (e64) {
                s = (int)((const long long*)edge)[i];
                d = (int)((const long long*)edge)[NE + i];
            } else {
                s = ((const int*)edge)[i];
                d = ((const int*)edge)[NE + i];
            }
        } else {
            s = i - NE; d = i - NE;
        }
        g_src[i] = s; g_dstv[i] = d;
        atomicAdd(&g_counts[d], 1);
        if (i < NN) {
            int b = b64 ? (int)((const long long*)batch)[i]
                        : ((const int*)batch)[i];
            g_batch[i] = b;
            atomicAdd(&g_gcnt[b], 1);
        }
    }
}

// ---------------- one-block exclusive scan over counts -> row offsets ----------------
__global__ void scan_kernel() {
    __shared__ int sums[1024];
    const int PER = (NN + 1023) / 1024;
    int t = threadIdx.x;
    int b0 = t * PER;
    int s = 0;
    for (int i = 0; i < PER; i++) {
        int idx = b0 + i;
        if (idx < NN) s += g_counts[idx];
    }
    sums[t] = s;
    __syncthreads();
    // Hillis-Steele inclusive scan
    for (int off = 1; off < 1024; off <<= 1) {
        int v = (t >= off) ? sums[t - off] : 0;
        __syncthreads();
        sums[t] += v;
        __syncthreads();
    }
    int run = sums[t] - s;   // exclusive prefix for this thread's range
    for (int i = 0; i < PER; i++) {
        int idx = b0 + i;
        if (idx < NN) {
            int c = g_counts[idx];
            g_roff[idx] = run;
            g_cursor[idx] = run;
            run += c;
        }
    }
    if (t == 1023) g_roff[NN] = run;
}

__global__ void fill_kernel() {
    int i = blockIdx.x * blockDim.x + threadIdx.x;
    if (i >= ET) return;
    int d = g_dstv[i];
    int p = atomicAdd(&g_cursor[d], 1);
    g_csr[p] = g_src[i];
}

// ---------------- SGEMM + fused alpha epilogue ----------------
// C[M,128] = A[M,K] @ B[K,128]; also g_as[m] = C[m,:].asrc, g_ad[m] = C[m,:].adst
template <int K>
__global__ void __launch_bounds__(256)
gemm_kernel(const float* __restrict__ A, const float* __restrict__ B,
            float* __restrict__ C, int M,
            const float* __restrict__ asrc, const float* __restrict__ adst) {
    const int BM = 64, BN = 128, BK = 16;
    __shared__ float As[BK][BM];
    __shared__ float Bs[BK][BN];
    int tid = threadIdx.x;
    int m0 = blockIdx.x * BM;
    int ty = tid >> 5;
    int tx = tid & 31;

    float acc[8][4];
#pragma unroll
    for (int i = 0; i < 8; i++)
#pragma unroll
        for (int j = 0; j < 4; j++) acc[i][j] = 0.f;

    int arow = tid >> 2;
    int ak4  = (tid & 3) * 4;
    int bn4  = (tid & 31) * 4;
    int bk   = tid >> 5;

    for (int k0 = 0; k0 < K; k0 += BK) {
        float4 av = make_float4(0.f, 0.f, 0.f, 0.f);
        int gm = m0 + arow;
        if (gm < M) av = *(const float4*)(A + (size_t)gm * K + k0 + ak4);
        As[ak4 + 0][arow] = av.x; As[ak4 + 1][arow] = av.y;
        As[ak4 + 2][arow] = av.z; As[ak4 + 3][arow] = av.w;

        float4 bv0 = *(const float4*)(B + (size_t)(k0 + bk) * BN + bn4);
        float4 bv1 = *(const float4*)(B + (size_t)(k0 + bk + 8) * BN + bn4);
        *(float4*)&Bs[bk][bn4]     = bv0;
        *(float4*)&Bs[bk + 8][bn4] = bv1;
        __syncthreads();

#pragma unroll
        for (int k = 0; k < BK; k++) {
            float4 b4 = *(const float4*)&Bs[k][tx * 4];
            float4 a0 = *(const float4*)&As[k][ty * 8];
            float4 a1 = *(const float4*)&As[k][ty * 8 + 4];
            float a[8] = {a0.x, a0.y, a0.z, a0.w, a1.x, a1.y, a1.z, a1.w};
#pragma unroll
            for (int i = 0; i < 8; i++) {
                acc[i][0] += a[i] * b4.x;
                acc[i][1] += a[i] * b4.y;
                acc[i][2] += a[i] * b4.z;
                acc[i][3] += a[i] * b4.w;
            }
        }
        __syncthreads();
    }

    float4 asv = ((const float4*)asrc)[tx];
    float4 adv = ((const float4*)adst)[tx];
#pragma unroll
    for (int i = 0; i < 8; i++) {
        int gm = m0 + ty * 8 + i;
        float s = acc[i][0] * asv.x + acc[i][1] * asv.y +
                  acc[i][2] * asv.z + acc[i][3] * asv.w;
        float d = acc[i][0] * adv.x + acc[i][1] * adv.y +
                  acc[i][2] * adv.z + acc[i][3] * adv.w;
#pragma unroll
        for (int o = 16; o; o >>= 1) {
            s += __shfl_xor_sync(0xffffffffu, s, o);
            d += __shfl_xor_sync(0xffffffffu, d, o);
        }
        if (gm < M) {
            *(float4*)(C + (size_t)gm * BN + tx * 4) =
                make_float4(acc[i][0], acc[i][1], acc[i][2], acc[i][3]);
            if (tx == 0) { g_as[gm] = s; g_ad[gm] = d; }
        }
    }
}

// ---------------- fused attention softmax + aggregate (+bias/relu/pool) ----------------
// warp per destination node
template <int POOL>
__global__ void __launch_bounds__(256)
attn_kernel(const float* __restrict__ h, const float* __restrict__ bias,
            float* __restrict__ out) {
    int d = blockIdx.x * 8 + (threadIdx.x >> 5);
    if (d >= NN) return;
    int lane = threadIdx.x & 31;
    int beg = g_roff[d], end = g_roff[d + 1];
    float add = g_ad[d];

    // pass 1: max
    float mx = -INFINITY;
    for (int i = beg + lane; i < end; i += 32) {
        float e = g_as[g_csr[i]] + add;
        e = e > 0.f ? e : NEG_SLOPE * e;
        mx = fmaxf(mx, e);
    }
#pragma unroll
    for (int o = 16; o; o >>= 1) mx = fmaxf(mx, __shfl_xor_sync(0xffffffffu, mx, o));

    // pass 2: denominator
    float den = 0.f;
    for (int i = beg + lane; i < end; i += 32) {
        float e = g_as[g_csr[i]] + add;
        e = e > 0.f ? e : NEG_SLOPE * e;
        den += __expf(e - mx);
    }
#pragma unroll
    for (int o = 16; o; o >>= 1) den += __shfl_xor_sync(0xffffffffu, den, o);
    float inv = 1.f / den;

    // pass 3: weighted aggregation, whole warp per edge (float4 per lane)
    float4 acc = make_float4(0.f, 0.f, 0.f, 0.f);
    for (int i = beg; i < end; i++) {
        int s = g_csr[i];
        float e = g_as[s] + add;
        e = e > 0.f ? e : NEG_SLOPE * e;
        float c = __expf(e - mx) * inv;
        float4 hv = ((const float4*)(h + (size_t)s * HID))[lane];
        acc.x += c * hv.x; acc.y += c * hv.y;
        acc.z += c * hv.z; acc.w += c * hv.w;
    }

    float4 bb = ((const float4*)bias)[lane];
    acc.x = fmaxf(acc.x + bb.x, 0.f);
    acc.y = fmaxf(acc.y + bb.y, 0.f);
    acc.z = fmaxf(acc.z + bb.z, 0.f);
    acc.w = fmaxf(acc.w + bb.w, 0.f);

    if (POOL) {
        int g = g_batch[d];
        float* p = g_pool + g * HID + lane * 4;
        atomicAdd(p + 0, acc.x);
        atomicAdd(p + 1, acc.y);
        atomicAdd(p + 2, acc.z);
        atomicAdd(p + 3, acc.w);
    } else {
        ((float4*)(out + (size_t)d * HID))[lane] = acc;
    }
}

// ---------------- classifier head ----------------
__global__ void head_kernel(const float* __restrict__ Wc,
                            const float* __restrict__ bc,
                            float* __restrict__ out) {
    int g = blockIdx.x;
    int lane = threadIdx.x;
    float s = 0.f;
#pragma unroll
    for (int j = lane; j < HID; j += 32) s += g_pool[g * HID + j] * Wc[j];
#pragma unroll
    for (int o = 16; o; o >>= 1) s += __shfl_xor_sync(0xffffffffu, s, o);
    if (lane == 0) {
        float c = fmaxf((float)g_gcnt[g], 1.f);
        float v = s / c + bc[0];
        out[g] = 1.f / (1.f + expf(-v));
    }
}

// ---------------- launch ----------------
extern "C" void kernel_launch(void* const* d_in, const int* in_sizes, int n_in,
                              void* d_out, int out_size) {
    const float* x    = (const float*)d_in[0];
    const void*  edge = d_in[1];
    const void*  batch= d_in[2];
    const float* W1   = (const float*)d_in[3];
    const float* as1  = (const float*)d_in[4];
    const float* ad1  = (const float*)d_in[5];
    const float* b1   = (const float*)d_in[6];
    const float* W2   = (const float*)d_in[7];
    const float* as2  = (const float*)d_in[8];
    const float* ad2  = (const float*)d_in[9];
    const float* b2   = (const float*)d_in[10];
    const float* Wc   = (const float*)d_in[11];
    const float* bc   = (const float*)d_in[12];
    float* out = (float*)d_out;
    (void)in_sizes; (void)n_in; (void)out_size;

    float* bufA; cudaGetSymbolAddress((void**)&bufA, g_bufA);
    float* bufB; cudaGetSymbolAddress((void**)&bufB, g_bufB);

    const int EB = (ET + 255) / 256;
    const int WB = (NN + 7) / 8;

    detect_kernel<<<1, 32>>>((const unsigned*)edge, (const unsigned*)batch);
    zero_kernel<<<64, 256>>>();
    convert_kernel<<<EB, 256>>>(edge, batch);
    scan_kernel<<<1, 1024>>>();
    fill_kernel<<<EB, 256>>>();

    // ---- layer 1 ----
    gemm_kernel<IND><<<(NN + 63) / 64, 256>>>(x, W1, bufA, NN, as1, ad1);
    attn_kernel<0><<<WB, 256>>>(bufA, b1, bufB);

    // ---- layer 2 ----
    gemm_kernel<HID><<<(NN + 63) / 64, 256>>>(bufB, W2, bufA, NN, as2, ad2);
    attn_kernel<1><<<WB, 256>>>(bufA, b2, nullptr);

    head_kernel<<<NG, 32>>>(Wc, bc, out);
}

// round 3
// speedup vs baseline: 2.0516x; 1.3365x over previous
#include <cuda_runtime.h>
#include <math.h>

#define NN   50000
#define NE   800000
#define ET   850000   // NE + NN self loops
#define IND  256
#define HID  128
#define NG   64
#define NEG_SLOPE 0.2f
#define SCAN_B ((NN + 255) / 256)   // 196

// ---------------- scratch (no allocations allowed) ----------------
__device__ float g_bufA[NN * HID];   // 25.6 MB
__device__ float g_bufB[NN * HID];   // 25.6 MB
__device__ float g_as[NN];
__device__ float g_ad[NN];
__device__ float g_w[ET];
__device__ int   g_src[ET];
__device__ int   g_dstv[ET];
__device__ int   g_batch[NN];
__device__ int   g_counts[NN];
__device__ int   g_roff[NN + 1];
__device__ int   g_cursor[NN];
__device__ int   g_csr[ET];          // src node id per CSR slot (grouped by dst)
__device__ int   g_bsum[SCAN_B];
__device__ int   g_boff[SCAN_B];
__device__ float g_pool[NG * HID];
__device__ int   g_gcnt[NG];
__device__ int   g_flag[2];

// ---------------- dtype sniffing (int64 vs int32) ----------------
__global__ void detect_kernel(const unsigned* __restrict__ e,
                              const unsigned* __restrict__ b) {
    if (threadIdx.x == 0 && blockIdx.x == 0) {
        int nz = 0;
        for (int i = 0; i < 1024; i++) nz += (e[2 * i + 1] != 0u);
        g_flag[0] = (nz == 0);
        nz = 0;
        for (int i = 0; i < 256; i++) nz += (b[NN - 1 - 2 * i] != 0u);
        g_flag[1] = (nz == 0);
    }
}

// ---------------- zero small scratch ----------------
__global__ void zero_kernel() {
    int stride = gridDim.x * blockDim.x;
    int i0 = blockIdx.x * blockDim.x + threadIdx.x;
    for (int j = i0; j < NN; j += stride) g_counts[j] = 0;
    for (int j = i0; j < NG * HID; j += stride) g_pool[j] = 0.f;
    for (int j = i0; j < NG; j += stride) g_gcnt[j] = 0;
}

// ---------------- convert + histogram + per-graph counts ----------------
__global__ void convert_kernel(const void* __restrict__ edge,
                               const void* __restrict__ batch) {
    int e64 = g_flag[0], b64 = g_flag[1];
    int stride = gridDim.x * blockDim.x;
    for (int i = blockIdx.x * blockDim.x + threadIdx.x; i < ET; i += stride) {
        int s, d;
        if (i < NE) {
            if (e64) {
                s = (int)((const long long*)edge)[i];
                d = (int)((const long long*)edge)[NE + i];
            } else {
                s = ((const int*)edge)[i];
                d = ((const int*)edge)[NE + i];
            }
        } else {
            s = i - NE; d = i - NE;
        }
        g_src[i] = s; g_dstv[i] = d;
        atomicAdd(&g_counts[d], 1);
        if (i < NN) {
            int b = b64 ? (int)((const long long*)batch)[i]
                        : ((const int*)batch)[i];
            g_batch[i] = b;
            atomicAdd(&g_gcnt[b], 1);
        }
    }
}

// ---------------- parallel exclusive scan (3 kernels) ----------------
__global__ void scanA_kernel() {
    __shared__ int ws[8];
    int i = blockIdx.x * 256 + threadIdx.x;
    int lane = threadIdx.x & 31, wrp = threadIdx.x >> 5;
    int v = (i < NN) ? g_counts[i] : 0;
    int incl = v;
#pragma unroll
    for (int o = 1; o < 32; o <<= 1) {
        int t = __shfl_up_sync(0xffffffffu, incl, o);
        if (lane >= o) incl += t;
    }
    if (lane == 31) ws[wrp] = incl;
    __syncthreads();
    if (threadIdx.x < 8) {
        int s = ws[threadIdx.x];
        int inc2 = s;
#pragma unroll
        for (int o = 1; o < 8; o <<= 1) {
            int t = __shfl_up_sync(0xffu, inc2, o);
            if (threadIdx.x >= (unsigned)o) inc2 += t;
        }
        ws[threadIdx.x] = inc2 - s;               // exclusive warp offset
        if (threadIdx.x == 7) g_bsum[blockIdx.x] = inc2;   // block total
    }
    __syncthreads();
    if (i < NN) g_roff[i] = ws[wrp] + incl - v;   // block-local exclusive
}

__global__ void scanB_kernel() {
    __shared__ int ws[8];
    int t = threadIdx.x;
    int lane = t & 31, wrp = t >> 5;
    int v = (t < SCAN_B) ? g_bsum[t] : 0;
    int incl = v;
#pragma unroll
    for (int o = 1; o < 32; o <<= 1) {
        int x = __shfl_up_sync(0xffffffffu, incl, o);
        if (lane >= o) incl += x;
    }
    if (lane == 31) ws[wrp] = incl;
    __syncthreads();
    if (t < 8) {
        int s = ws[t];
        int inc2 = s;
#pragma unroll
        for (int o = 1; o < 8; o <<= 1) {
            int x = __shfl_up_sync(0xffu, inc2, o);
            if (t >= o) inc2 += x;
        }
        ws[t] = inc2 - s;
    }
    __syncthreads();
    if (t < SCAN_B) g_boff[t] = ws[wrp] + incl - v;
}

__global__ void scanC_kernel() {
    int i = blockIdx.x * 256 + threadIdx.x;
    if (i == 0) g_roff[NN] = ET;
    if (i >= NN) return;
    int r = g_roff[i] + g_boff[i >> 8];
    g_roff[i] = r;
    g_cursor[i] = r;
}

__global__ void fill_kernel() {
    int i = blockIdx.x * blockDim.x + threadIdx.x;
    if (i >= ET) return;
    int d = g_dstv[i];
    int p = atomicAdd(&g_cursor[d], 1);
    g_csr[p] = g_src[i];
}

// ---------------- SGEMM + fused alpha epilogue ----------------
template <int K>
__global__ void __launch_bounds__(256)
gemm_kernel(const float* __restrict__ A, const float* __restrict__ B,
            float* __restrict__ C, int M,
            const float* __restrict__ asrc, const float* __restrict__ adst) {
    const int BM = 64, BN = 128, BK = 16;
    __shared__ float As[BK][BM];
    __shared__ float Bs[BK][BN];
    int tid = threadIdx.x;
    int m0 = blockIdx.x * BM;
    int ty = tid >> 5;
    int tx = tid & 31;

    float acc[8][4];
#pragma unroll
    for (int i = 0; i < 8; i++)
#pragma unroll
        for (int j = 0; j < 4; j++) acc[i][j] = 0.f;

    int arow = tid >> 2;
    int ak4  = (tid & 3) * 4;
    int bn4  = (tid & 31) * 4;
    int bk   = tid >> 5;

    for (int k0 = 0; k0 < K; k0 += BK) {
        float4 av = make_float4(0.f, 0.f, 0.f, 0.f);
        int gm = m0 + arow;
        if (gm < M) av = *(const float4*)(A + (size_t)gm * K + k0 + ak4);
        As[ak4 + 0][arow] = av.x; As[ak4 + 1][arow] = av.y;
        As[ak4 + 2][arow] = av.z; As[ak4 + 3][arow] = av.w;

        float4 bv0 = *(const float4*)(B + (size_t)(k0 + bk) * BN + bn4);
        float4 bv1 = *(const float4*)(B + (size_t)(k0 + bk + 8) * BN + bn4);
        *(float4*)&Bs[bk][bn4]     = bv0;
        *(float4*)&Bs[bk + 8][bn4] = bv1;
        __syncthreads();

#pragma unroll
        for (int k = 0; k < BK; k++) {
            float4 b4 = *(const float4*)&Bs[k][tx * 4];
            float4 a0 = *(const float4*)&As[k][ty * 8];
            float4 a1 = *(const float4*)&As[k][ty * 8 + 4];
            float a[8] = {a0.x, a0.y, a0.z, a0.w, a1.x, a1.y, a1.z, a1.w};
#pragma unroll
            for (int i = 0; i < 8; i++) {
                acc[i][0] += a[i] * b4.x;
                acc[i][1] += a[i] * b4.y;
                acc[i][2] += a[i] * b4.z;
                acc[i][3] += a[i] * b4.w;
            }
        }
        __syncthreads();
    }

    float4 asv = ((const float4*)asrc)[tx];
    float4 adv = ((const float4*)adst)[tx];
#pragma unroll
    for (int i = 0; i < 8; i++) {
        int gm = m0 + ty * 8 + i;
        float s = acc[i][0] * asv.x + acc[i][1] * asv.y +
                  acc[i][2] * asv.z + acc[i][3] * asv.w;
        float d = acc[i][0] * adv.x + acc[i][1] * adv.y +
                  acc[i][2] * adv.z + acc[i][3] * adv.w;
#pragma unroll
        for (int o = 16; o; o >>= 1) {
            s += __shfl_xor_sync(0xffffffffu, s, o);
            d += __shfl_xor_sync(0xffffffffu, d, o);
        }
        if (gm < M) {
            *(float4*)(C + (size_t)gm * BN + tx * 4) =
                make_float4(acc[i][0], acc[i][1], acc[i][2], acc[i][3]);
            if (tx == 0) { g_as[gm] = s; g_ad[gm] = d; }
        }
    }
}

// ---------------- fused attention softmax + aggregate (+bias/relu/pool) ----------------
// warp per destination node; no max-pass (exp safe in fp32 here)
template <int POOL>
__global__ void __launch_bounds__(256)
attn_kernel(const float* __restrict__ h, const float* __restrict__ bias,
            float* __restrict__ out) {
    int d = blockIdx.x * 8 + (threadIdx.x >> 5);
    if (d >= NN) return;
    int lane = threadIdx.x & 31;
    int beg = g_roff[d], end = g_roff[d + 1];
    float add = g_ad[d];

    // pass A: w = exp(leakyrelu(e)), cache in g_w, accumulate denominator
    float den = 0.f;
    for (int i = beg + lane; i < end; i += 32) {
        float e = g_as[g_csr[i]] + add;
        e = e > 0.f ? e : NEG_SLOPE * e;
        float w = __expf(e);
        g_w[i] = w;
        den += w;
    }
#pragma unroll
    for (int o = 16; o; o >>= 1) den += __shfl_xor_sync(0xffffffffu, den, o);
    float inv = 1.f / den;
    __syncwarp();

    // pass B: weighted aggregation; csr/w loads are warp-uniform (broadcast)
    float4 acc = make_float4(0.f, 0.f, 0.f, 0.f);
    for (int i = beg; i < end; i++) {
        int s = g_csr[i];
        float c = g_w[i] * inv;
        float4 hv = ((const float4*)(h + (size_t)s * HID))[lane];
        acc.x += c * hv.x; acc.y += c * hv.y;
        acc.z += c * hv.z; acc.w += c * hv.w;
    }

    float4 bb = ((const float4*)bias)[lane];
    acc.x = fmaxf(acc.x + bb.x, 0.f);
    acc.y = fmaxf(acc.y + bb.y, 0.f);
    acc.z = fmaxf(acc.z + bb.z, 0.f);
    acc.w = fmaxf(acc.w + bb.w, 0.f);

    if (POOL) {
        int g = g_batch[d];
        float* p = g_pool + g * HID + lane * 4;
        atomicAdd(p + 0, acc.x);
        atomicAdd(p + 1, acc.y);
        atomicAdd(p + 2, acc.z);
        atomicAdd(p + 3, acc.w);
    } else {
        ((float4*)(out + (size_t)d * HID))[lane] = acc;
    }
}

// ---------------- classifier head ----------------
__global__ void head_kernel(const float* __restrict__ Wc,
                            const float* __restrict__ bc,
                            float* __restrict__ out) {
    int g = blockIdx.x;
    int lane = threadIdx.x;
    float s = 0.f;
#pragma unroll
    for (int j = lane; j < HID; j += 32) s += g_pool[g * HID + j] * Wc[j];
#pragma unroll
    for (int o = 16; o; o >>= 1) s += __shfl_xor_sync(0xffffffffu, s, o);
    if (lane == 0) {
        float c = fmaxf((float)g_gcnt[g], 1.f);
        float v = s / c + bc[0];
        out[g] = 1.f / (1.f + expf(-v));
    }
}

// ---------------- launch ----------------
extern "C" void kernel_launch(void* const* d_in, const int* in_sizes, int n_in,
                              void* d_out, int out_size) {
    const float* x    = (const float*)d_in[0];
    const void*  edge = d_in[1];
    const void*  batch= d_in[2];
    const float* W1   = (const float*)d_in[3];
    const float* as1  = (const float*)d_in[4];
    const float* ad1  = (const float*)d_in[5];
    const float* b1   = (const float*)d_in[6];
    const float* W2   = (const float*)d_in[7];
    const float* as2  = (const float*)d_in[8];
    const float* ad2  = (const float*)d_in[9];
    const float* b2   = (const float*)d_in[10];
    const float* Wc   = (const float*)d_in[11];
    const float* bc   = (const float*)d_in[12];
    float* out = (float*)d_out;
    (void)in_sizes; (void)n_in; (void)out_size;

    float* bufA; cudaGetSymbolAddress((void**)&bufA, g_bufA);
    float* bufB; cudaGetSymbolAddress((void**)&bufB, g_bufB);

    const int EB = (ET + 255) / 256;
    const int WB = (NN + 7) / 8;

    detect_kernel<<<1, 32>>>((const unsigned*)edge, (const unsigned*)batch);
    zero_kernel<<<64, 256>>>();
    convert_kernel<<<EB, 256>>>(edge, batch);
    scanA_kernel<<<SCAN_B, 256>>>();
    scanB_kernel<<<1, 256>>>();
    scanC_kernel<<<SCAN_B, 256>>>();
    fill_kernel<<<EB, 256>>>();

    // ---- layer 1 ----
    gemm_kernel<IND><<<(NN + 63) / 64, 256>>>(x, W1, bufA, NN, as1, ad1);
    attn_kernel<0><<<WB, 256>>>(bufA, b1, bufB);

    // ---- layer 2 ----
    gemm_kernel<HID><<<(NN + 63) / 64, 256>>>(bufB, W2, bufA, NN, as2, ad2);
    attn_kernel<1><<<WB, 256>>>(bufA, b2, nullptr);

    head_kernel<<<NG, 32>>>(Wc, bc, out);
}